// round 10
// baseline (speedup 1.0000x reference)
#include <cuda_runtime.h>
#include <cuda_bf16.h>
#include <cstdint>

// GraphSAGE on GB300 via mma.sync bf16 hi/lo (3-MMA fp32 emulation).
// R10: gather fully via cp.async (self-copy/self-consume per thread, prefetch
// distance 2, raw triple-buffer), adj staged once in smem. KC=16, 32 chunks.

#define N_NODES 100000
#define DIM     256
#define KDIM    512
#define NNEIGH  10
#define BM      32
#define KC      16
#define NCHUNK  32
#define THREADS 256

// smem byte offsets
#define ADJ_OFF  0                 // 320 ints = 1280 B
#define A_OFF    2048              // 2 x 4096  (32 rows x 128B: hi 0-31 | lo 64-95)
#define W_OFF    10240             // 2 x 16384 (hi 8K | lo 8K)
#define RAW_OFF  43008             // 3 x 22528 (32 rows x 704B: 10 nb x 64B...)
#define RAW_STRIDE 704
#define RAW_BUF  22528
#define SMEM_TOTAL (RAW_OFF + 3 * RAW_BUF)   // 110592

__device__ float g_buf0[(size_t)N_NODES * DIM];
__device__ float g_buf1[(size_t)N_NODES * DIM];
// W fragments in mma B-frag order: [layer][ktile(32)][ntile(32)][lane(32)][2] u32
__device__ uint32_t g_wfrag_hi[3][32 * 32 * 32 * 2];
__device__ uint32_t g_wfrag_lo[3][32 * 32 * 32 * 2];

__device__ __forceinline__ uint32_t smem_u32(const void* p) {
    uint32_t a;
    asm("{ .reg .u64 t; cvta.to.shared.u64 t, %1; cvt.u32.u64 %0, t; }" : "=r"(a) : "l"(p));
    return a;
}
__device__ __forceinline__ uint32_t sw128(uint32_t off) {
    return off ^ ((off >> 3) & 0x70);
}
__device__ __forceinline__ uint32_t pack_bf2(float a, float b) {
    __nv_bfloat162 t = __floats2bfloat162_rn(a, b);
    return *reinterpret_cast<uint32_t*>(&t);
}
__device__ __forceinline__ void ldmat4(uint32_t* r, uint32_t addr) {
    asm volatile("ldmatrix.sync.aligned.m8n8.x4.shared.b16 {%0,%1,%2,%3}, [%4];"
                 : "=r"(r[0]), "=r"(r[1]), "=r"(r[2]), "=r"(r[3]) : "r"(addr));
}
__device__ __forceinline__ void mma16816(float* c, const uint32_t* a, uint32_t b0, uint32_t b1) {
    asm volatile("mma.sync.aligned.m16n8k16.row.col.f32.bf16.bf16.f32 "
                 "{%0,%1,%2,%3}, {%4,%5,%6,%7}, {%8,%9}, {%0,%1,%2,%3};"
                 : "+f"(c[0]), "+f"(c[1]), "+f"(c[2]), "+f"(c[3])
                 : "r"(a[0]), "r"(a[1]), "r"(a[2]), "r"(a[3]), "r"(b0), "r"(b1));
}
__device__ __forceinline__ void cpasync16(uint32_t smem_dst, const void* gsrc) {
    asm volatile("cp.async.cg.shared.global [%0], [%1], 16;"
                 :: "r"(smem_dst), "l"(gsrc) : "memory");
}
__device__ __forceinline__ void cpasync_commit() {
    asm volatile("cp.async.commit_group;" ::: "memory");
}
__device__ __forceinline__ void cpasync_wait1() {
    asm volatile("cp.async.wait_group 1;" ::: "memory");
}
__device__ __forceinline__ void cpasync_wait0() {
    asm volatile("cp.async.wait_group 0;" ::: "memory");
}

// -------- W prep: hi/lo split into mma B-fragment order (32 ktiles x 16k) ----
__global__ void prep_wfrag(const float* __restrict__ W0, const float* __restrict__ W1,
                           const float* __restrict__ W2)
{
    int idx = blockIdx.x * blockDim.x + threadIdx.x;   // [layer][kt][nt][lane]
    if (idx >= 3 * 32 * 32 * 32) return;
    const int lane  = idx & 31;
    const int nt    = (idx >> 5) & 31;
    const int kt    = (idx >> 10) & 31;
    const int layer = idx >> 15;
    const float* W = layer == 0 ? W0 : (layer == 1 ? W1 : W2);
    const int k0 = kt * 16 + (lane & 3) * 2;
    const int n  = nt * 8 + (lane >> 2);

    float v[4] = { W[(k0 + 0) * DIM + n], W[(k0 + 1) * DIM + n],
                   W[(k0 + 8) * DIM + n], W[(k0 + 9) * DIM + n] };
    float hi[4], lo[4];
    #pragma unroll
    for (int i = 0; i < 4; ++i) {
        __nv_bfloat16 h = __float2bfloat16(v[i]);
        hi[i] = __bfloat162float(h);
        lo[i] = v[i] - hi[i];
    }
    const size_t base = ((size_t)(kt * 32 + nt) * 32 + lane) * 2;
    g_wfrag_hi[layer][base + 0] = pack_bf2(hi[0], hi[1]);
    g_wfrag_hi[layer][base + 1] = pack_bf2(hi[2], hi[3]);
    g_wfrag_lo[layer][base + 0] = pack_bf2(lo[0], lo[1]);
    g_wfrag_lo[layer][base + 1] = pack_bf2(lo[2], lo[3]);
}

// -------- fused SAGE layer --------
template <bool RELU>
__global__ __launch_bounds__(THREADS, 2)
void sage_mma(const float* __restrict__ hin, const int* __restrict__ adj,
              const uint32_t* __restrict__ wfh, const uint32_t* __restrict__ wfl,
              const float* __restrict__ bias, float* __restrict__ hout)
{
    extern __shared__ char smem[];
    const uint32_t sb = smem_u32(smem);
    const int tid  = threadIdx.x;
    const int lane = tid & 31;
    const int wn   = tid >> 5;           // warp n position (cols wn*32..+31)
    const int row0 = blockIdx.x * BM;

    // ---- stage adj rows for this block (320 ints) ----
    if (tid < 80)
        ((int4*)smem)[tid] = ((const int4*)(adj + (size_t)row0 * NNEIGH))[tid];
    __syncthreads();

    // ---- producer roles ----
    const bool isg = tid < 128;          // warps 0-3: gather; warps 4-7: W copy
    const int grow = tid >> 2;           // row 0..31 (gather threads)
    const int gseg = tid & 3;            // 16B segment (4 cols)
    uint32_t gb[NNEIGH];                 // neighbor row base (element index)
    uint32_t gbself = 0;
    if (isg) {
        const int* adjs = (const int*)smem;
        #pragma unroll
        for (int j = 0; j < NNEIGH; ++j)
            gb[j] = (uint32_t)adjs[grow * NNEIGH + j] * DIM + gseg * 4;
        gbself = (uint32_t)(row0 + grow) * DIM + gseg * 4;
    }
    const int ptid = tid - 128;          // W-copy thread id

    float c[2][4][4];
    #pragma unroll
    for (int i = 0; i < 2; ++i)
        #pragma unroll
        for (int j = 0; j < 4; ++j)
            #pragma unroll
            for (int k = 0; k < 4; ++k) c[i][j][k] = 0.f;

    // ---- raw gather copy: chunk cc into raw buffer bR (own segments only) ----
    auto rawcopy = [&](int cc, int bR) {
        if (isg) {
            const int colbase = (cc & 15) * KC;
            const uint32_t dst = sb + RAW_OFF + bR * RAW_BUF + grow * RAW_STRIDE + gseg * 16;
            if (cc < 16) {
                cpasync16(dst, hin + gbself + colbase);
            } else {
                #pragma unroll
                for (int j = 0; j < NNEIGH; ++j)
                    cpasync16(dst + j * 64, hin + gb[j] + colbase);
            }
        }
        cpasync_commit();
    };
    // ---- W copy: chunk cc into W buffer (cc&1) ----
    auto wcopy = [&](int cc) {
        if (!isg) {
            const uint32_t dst = sb + W_OFF + (cc & 1) * 16384;
            const uint32_t* srcH = wfh + (size_t)cc * 2048;
            const uint32_t* srcL = wfl + (size_t)cc * 2048;
            #pragma unroll
            for (int i = 0; i < 4; ++i) {
                const int e = ptid + i * 128;          // 512 x 16B per half
                cpasync16(dst + e * 16,        srcH + e * 4);
                cpasync16(dst + 8192 + e * 16, srcL + e * 4);
            }
        }
        cpasync_commit();
    };
    // ---- consume own raw data: mean + hi/lo split + A store ----
    auto consume = [&](int cc, int bR) {
        if (isg) {
            const char* rb = smem + RAW_OFF + bR * RAW_BUF + grow * RAW_STRIDE + gseg * 16;
            float4 s;
            if (cc < 16) {
                s = *(const float4*)rb;
            } else {
                s = make_float4(0.f, 0.f, 0.f, 0.f);
                #pragma unroll
                for (int j = 0; j < NNEIGH; ++j) {
                    const float4 q = *(const float4*)(rb + j * 64);
                    s.x += q.x; s.y += q.y; s.z += q.z; s.w += q.w;
                }
                s.x *= 0.1f; s.y *= 0.1f; s.z *= 0.1f; s.w *= 0.1f;
            }
            const __nv_bfloat16 hx = __float2bfloat16(s.x), hy = __float2bfloat16(s.y);
            const __nv_bfloat16 hz = __float2bfloat16(s.z), hw = __float2bfloat16(s.w);
            uint2 hv, lv;
            hv.x = pack_bf2(s.x, s.y);
            hv.y = pack_bf2(s.z, s.w);
            lv.x = pack_bf2(s.x - __bfloat162float(hx), s.y - __bfloat162float(hy));
            lv.y = pack_bf2(s.z - __bfloat162float(hz), s.w - __bfloat162float(hw));
            char* Ab = smem + A_OFF + (cc & 1) * 4096;
            *(uint2*)(Ab + sw128((uint32_t)(grow * 128 + gseg * 8)))      = hv;
            *(uint2*)(Ab + sw128((uint32_t)(grow * 128 + 64 + gseg * 8))) = lv;
        }
    };

    // ================= prologue =================
    rawcopy(0, 0);
    wcopy(0);
    rawcopy(1, 1);
    cpasync_wait1();     // raw0 done (gather warps), w0 done (W warps)
    consume(0, 0);
    __syncthreads();

    // ================= main loop =================
    int bufC = 1;        // raw buffer of chunk kc+1
    int bufR = 2;        // raw buffer for chunk kc+2
    for (int kc = 0; kc < NCHUNK; ++kc) {
        if (kc + 1 < NCHUNK) wcopy(kc + 1);
        if (kc + 2 < NCHUNK) rawcopy(kc + 2, bufR);

        // ---- MMA on chunk kc: 24 MMAs ----
        {
            const uint32_t Ab = sb + A_OFF + (kc & 1) * 4096;
            const char*    Wp = smem + W_OFF + (kc & 1) * 16384;
            uint32_t ah0[4], ah1[4], al0[4], al1[4];
            const uint32_t off0 = (uint32_t)((lane & 15) * 128 + (lane >> 4) * 16);
            ldmat4(ah0, Ab + sw128(off0));
            ldmat4(ah1, Ab + sw128(off0 + 2048));
            ldmat4(al0, Ab + sw128(off0 + 64));
            ldmat4(al1, Ab + sw128(off0 + 2048 + 64));

            const uint2* bhp = (const uint2*)(Wp + ((size_t)(wn * 4) * 32 + lane) * 8);
            const uint2* blp = (const uint2*)(Wp + 8192 + ((size_t)(wn * 4) * 32 + lane) * 8);
            uint2 b[4];
            #pragma unroll
            for (int nt = 0; nt < 4; ++nt) b[nt] = bhp[nt * 32];
            #pragma unroll
            for (int nt = 0; nt < 4; ++nt) {          // hh
                mma16816(c[0][nt], ah0, b[nt].x, b[nt].y);
                mma16816(c[1][nt], ah1, b[nt].x, b[nt].y);
            }
            #pragma unroll
            for (int nt = 0; nt < 4; ++nt) {          // lh
                mma16816(c[0][nt], al0, b[nt].x, b[nt].y);
                mma16816(c[1][nt], al1, b[nt].x, b[nt].y);
            }
            #pragma unroll
            for (int nt = 0; nt < 4; ++nt) b[nt] = blp[nt * 32];
            #pragma unroll
            for (int nt = 0; nt < 4; ++nt) {          // hl
                mma16816(c[0][nt], ah0, b[nt].x, b[nt].y);
                mma16816(c[1][nt], ah1, b[nt].x, b[nt].y);
            }
        }

        if (kc + 1 < NCHUNK) {
            if (kc + 2 < NCHUNK) cpasync_wait1();   // raw(kc+1)+w(kc+1) done
            else                 cpasync_wait0();
            consume(kc + 1, bufC);                   // own data only, no bar needed
            __syncthreads();                         // publish A(kc+1) + W(kc+1)
        }
        bufC = (bufC == 2) ? 0 : bufC + 1;
        bufR = (bufR == 2) ? 0 : bufR + 1;
    }

    // ================= epilogue =================
    float2 bias2[4];
    #pragma unroll
    for (int nt = 0; nt < 4; ++nt)
        bias2[nt] = *(const float2*)&bias[wn * 32 + nt * 8 + (lane & 3) * 2];

    #pragma unroll
    for (int mt = 0; mt < 2; ++mt) {
        const int rbase = row0 + mt * 16 + (lane >> 2);
        #pragma unroll
        for (int h = 0; h < 2; ++h) {
            const int row = rbase + h * 8;
            if (row < N_NODES) {
                #pragma unroll
                for (int nt = 0; nt < 4; ++nt) {
                    const int n = wn * 32 + nt * 8 + (lane & 3) * 2;
                    float2 o;
                    o.x = c[mt][nt][h * 2 + 0] + bias2[nt].x;
                    o.y = c[mt][nt][h * 2 + 1] + bias2[nt].y;
                    if (RELU) { o.x = fmaxf(o.x, 0.f); o.y = fmaxf(o.y, 0.f); }
                    *(float2*)(hout + (size_t)row * DIM + n) = o;
                }
            }
        }
    }
}

extern "C" void kernel_launch(void* const* d_in, const int* in_sizes, int n_in,
                              void* d_out, int out_size)
{
    const float* x   = (const float*)d_in[0];
    const int*   adj = (const int*)  d_in[1];
    const float* W0  = (const float*)d_in[2];
    const float* b0  = (const float*)d_in[3];
    const float* W1  = (const float*)d_in[4];
    const float* b1  = (const float*)d_in[5];
    const float* W2  = (const float*)d_in[6];
    const float* b2  = (const float*)d_in[7];
    float* out = (float*)d_out;

    void *p0, *p1, *pwh, *pwl;
    cudaGetSymbolAddress(&p0, g_buf0);
    cudaGetSymbolAddress(&p1, g_buf1);
    cudaGetSymbolAddress(&pwh, g_wfrag_hi);
    cudaGetSymbolAddress(&pwl, g_wfrag_lo);
    float* h1 = (float*)p0;
    float* h2 = (float*)p1;
    const uint32_t* wh = (const uint32_t*)pwh;
    const uint32_t* wl = (const uint32_t*)pwl;
    const size_t WSZ = 32 * 32 * 32 * 2;

    cudaFuncSetAttribute(sage_mma<true>,
                         cudaFuncAttributeMaxDynamicSharedMemorySize, SMEM_TOTAL);
    cudaFuncSetAttribute(sage_mma<false>,
                         cudaFuncAttributeMaxDynamicSharedMemorySize, SMEM_TOTAL);

    prep_wfrag<<<(3 * 32 * 32 * 32 + 255) / 256, 256>>>(W0, W1, W2);

    const int grid = N_NODES / BM;   // 3125
    sage_mma<true ><<<grid, THREADS, SMEM_TOTAL>>>(x,  adj, wh,           wl,           b0, h1);
    sage_mma<true ><<<grid, THREADS, SMEM_TOTAL>>>(h1, adj, wh + WSZ,     wl + WSZ,     b1, h2);
    sage_mma<false><<<grid, THREADS, SMEM_TOTAL>>>(h2, adj, wh + 2 * WSZ, wl + 2 * WSZ, b2, out);
}

// round 12
// speedup vs baseline: 1.4069x; 1.4069x over previous
#include <cuda_runtime.h>
#include <cuda_fp16.h>
#include <cstdint>

// GraphSAGE on GB300 via single fp16 mma.sync (R9 structure, 3x less tensor work).
// Precision experiment: fp16 rounding gives ~2-4e-4 rel err (< 1e-3 gate).
// CTA: BM=32, 256 thr, warp tile 32x32, KC=32, 16 chunks, 2 CTAs/SM.

#define N_NODES 100000
#define DIM     256
#define KDIM    512
#define NNEIGH  10
#define BM      32
#define KC      32
#define NCHUNK  16
#define THREADS 256

// smem (bytes)
#define ABUF    4096             // 32 rows x 128B (fp16 data in first 64B)
#define WBASE   8192
#define WBUF    16384            // per W buffer (fp16 fragments, 16KB/chunk)
#define SMEM_TOTAL (WBASE + 2 * WBUF)   // 40960

__device__ float g_buf0[(size_t)N_NODES * DIM];
__device__ float g_buf1[(size_t)N_NODES * DIM];
// W fp16 fragments in mma B-frag order: [layer][ktile(32)][ntile(32)][lane(32)][2] u32
__device__ uint32_t g_wfrag[3][32 * 32 * 32 * 2];

__device__ __forceinline__ uint32_t smem_u32(const void* p) {
    uint32_t a;
    asm("{ .reg .u64 t; cvta.to.shared.u64 t, %1; cvt.u32.u64 %0, t; }" : "=r"(a) : "l"(p));
    return a;
}
__device__ __forceinline__ uint32_t sw128(uint32_t off) {
    return off ^ ((off >> 3) & 0x70);
}
__device__ __forceinline__ uint32_t pack_h2(float a, float b) {
    __half2 t = __floats2half2_rn(a, b);
    return *reinterpret_cast<uint32_t*>(&t);
}
__device__ __forceinline__ void ldmat4(uint32_t* r, uint32_t addr) {
    asm volatile("ldmatrix.sync.aligned.m8n8.x4.shared.b16 {%0,%1,%2,%3}, [%4];"
                 : "=r"(r[0]), "=r"(r[1]), "=r"(r[2]), "=r"(r[3]) : "r"(addr));
}
__device__ __forceinline__ void mma16816(float* c, const uint32_t* a, uint32_t b0, uint32_t b1) {
    asm volatile("mma.sync.aligned.m16n8k16.row.col.f32.f16.f16.f32 "
                 "{%0,%1,%2,%3}, {%4,%5,%6,%7}, {%8,%9}, {%0,%1,%2,%3};"
                 : "+f"(c[0]), "+f"(c[1]), "+f"(c[2]), "+f"(c[3])
                 : "r"(a[0]), "r"(a[1]), "r"(a[2]), "r"(a[3]), "r"(b0), "r"(b1));
}
__device__ __forceinline__ void cpasync16(uint32_t smem_dst, const void* gsrc) {
    asm volatile("cp.async.cg.shared.global [%0], [%1], 16;"
                 :: "r"(smem_dst), "l"(gsrc) : "memory");
}
__device__ __forceinline__ void cpasync_commit() {
    asm volatile("cp.async.commit_group;" ::: "memory");
}
__device__ __forceinline__ void cpasync_wait0() {
    asm volatile("cp.async.wait_group 0;" ::: "memory");
}

// -------- W prep: fp16 convert into mma B-fragment order --------
__global__ void prep_wfrag(const float* __restrict__ W0, const float* __restrict__ W1,
                           const float* __restrict__ W2)
{
    int idx = blockIdx.x * blockDim.x + threadIdx.x;   // [layer][kt][nt][lane]
    if (idx >= 3 * 32 * 32 * 32) return;
    const int lane  = idx & 31;
    const int nt    = (idx >> 5) & 31;
    const int kt    = (idx >> 10) & 31;
    const int layer = idx >> 15;
    const float* W = layer == 0 ? W0 : (layer == 1 ? W1 : W2);
    const int k0 = kt * 16 + (lane & 3) * 2;
    const int n  = nt * 8 + (lane >> 2);

    float v[4] = { W[(k0 + 0) * DIM + n], W[(k0 + 1) * DIM + n],
                   W[(k0 + 8) * DIM + n], W[(k0 + 9) * DIM + n] };
    const size_t base = ((size_t)(kt * 32 + nt) * 32 + lane) * 2;
    g_wfrag[layer][base + 0] = pack_h2(v[0], v[1]);
    g_wfrag[layer][base + 1] = pack_h2(v[2], v[3]);
}

// -------- fused SAGE layer --------
template <bool RELU>
__global__ __launch_bounds__(THREADS, 2)
void sage_mma(const float* __restrict__ hin, const int* __restrict__ adj,
              const uint32_t* __restrict__ wf,
              const float* __restrict__ bias, float* __restrict__ hout)
{
    extern __shared__ char smem[];
    const uint32_t sb = smem_u32(smem);
    const int tid  = threadIdx.x;
    const int lane = tid & 31;
    const int wn   = tid >> 5;       // warp n position (cols wn*32..+31)
    const int row0 = blockIdx.x * BM;

    // producer mapping: 8 threads/row, 4 cols each
    const int pr = tid >> 3;         // row 0..31
    const int pq = tid & 7;          // 4-col slice of the 32-col chunk
    const int prow = row0 + pr;
    const bool pvalid = prow < N_NODES;   // always true (100000 % 32 == 0)

    float c[2][4][4];
    #pragma unroll
    for (int i = 0; i < 2; ++i)
        #pragma unroll
        for (int j = 0; j < 4; ++j)
            #pragma unroll
            for (int k = 0; k < 4; ++k) c[i][j][k] = 0.f;

    // ---- gather issue: LDGs into rw (held across the MMA block) ----
    auto issue = [&](int kc, float4* rw) {
        const int col = (kc & 7) * KC + pq * 4;
        if (!pvalid) return;
        if (kc < 8) {
            rw[0] = *(const float4*)(hin + (size_t)prow * DIM + col);
        } else {
            const int* arow = adj + (size_t)prow * NNEIGH;
            int na[NNEIGH];
            #pragma unroll
            for (int j = 0; j < NNEIGH; j += 2) {
                const int2 p = *(const int2*)(arow + j);
                na[j] = p.x; na[j + 1] = p.y;
            }
            #pragma unroll
            for (int j = 0; j < NNEIGH; ++j)
                rw[j] = *(const float4*)(hin + (size_t)na[j] * DIM + col);
        }
    };
    // ---- gather consume: mean, fp16 convert, swizzled A store ----
    auto consume = [&](int kc, const float4* rw) {
        float4 s = make_float4(0.f, 0.f, 0.f, 0.f);
        if (pvalid) {
            if (kc < 8) s = rw[0];
            else {
                #pragma unroll
                for (int j = 0; j < NNEIGH; ++j) {
                    s.x += rw[j].x; s.y += rw[j].y; s.z += rw[j].z; s.w += rw[j].w;
                }
                s.x *= 0.1f; s.y *= 0.1f; s.z *= 0.1f; s.w *= 0.1f;
            }
        }
        uint2 hv;
        hv.x = pack_h2(s.x, s.y);
        hv.y = pack_h2(s.z, s.w);
        char* Ab = smem + (kc & 1) * ABUF;
        *(uint2*)(Ab + sw128((uint32_t)(pr * 128 + pq * 8))) = hv;
    };
    // ---- W chunk slab via cp.async (16KB) ----
    auto wcopy = [&](int kc) {
        const uint32_t dst = sb + WBASE + (kc & 1) * WBUF;
        const uint4* src = (const uint4*)(wf + (size_t)kc * 4096);
        #pragma unroll
        for (int i = 0; i < 4; ++i) {
            const int e = tid + i * THREADS;      // 1024 uint4 total
            cpasync16(dst + e * 16, src + e);
        }
        cpasync_commit();
    };

    // ================= prologue =================
    wcopy(0);
    {
        float4 rw[NNEIGH];
        issue(0, rw);
        consume(0, rw);
    }
    cpasync_wait0();
    __syncthreads();

    // ================= main loop =================
    for (int kc = 0; kc < NCHUNK; ++kc) {
        const bool nxt = kc + 1 < NCHUNK;
        float4 rw[NNEIGH];
        if (nxt) {
            wcopy(kc + 1);
            issue(kc + 1, rw);   // LDGs in flight across the MMA block
        }

        // ---- MMA on chunk kc: 2 kt x 8 = 16 MMAs ----
        const uint32_t Ab = sb + (kc & 1) * ABUF;
        const char*    Wp = smem + WBASE + (kc & 1) * WBUF;
        #pragma unroll
        for (int kt = 0; kt < 2; ++kt) {
            uint32_t a0[4], a1[4];
            const uint32_t off0 = (uint32_t)((lane & 15) * 128 + kt * 32 + (lane >> 4) * 16);
            ldmat4(a0, Ab + sw128(off0));
            ldmat4(a1, Ab + sw128(off0 + 16 * 128));

            const uint2* bp = (const uint2*)(Wp + ((size_t)(kt * 32 + wn * 4) * 32 + lane) * 8);
            uint2 b[4];
            #pragma unroll
            for (int nt = 0; nt < 4; ++nt) b[nt] = bp[nt * 32];
            #pragma unroll
            for (int nt = 0; nt < 4; ++nt) {          // 8 independent accumulators
                mma16816(c[0][nt], a0, b[nt].x, b[nt].y);
                mma16816(c[1][nt], a1, b[nt].x, b[nt].y);
            }
        }

        if (nxt) {
            consume(kc + 1, rw);   // data arrived during the MMA block
            cpasync_wait0();
        }
        __syncthreads();
    }

    // ================= epilogue =================
    float2 bias2[4];
    #pragma unroll
    for (int nt = 0; nt < 4; ++nt)
        bias2[nt] = *(const float2*)&bias[wn * 32 + nt * 8 + (lane & 3) * 2];

    #pragma unroll
    for (int mt = 0; mt < 2; ++mt) {
        const int rbase = row0 + mt * 16 + (lane >> 2);
        #pragma unroll
        for (int h = 0; h < 2; ++h) {
            const int row = rbase + h * 8;
            if (row < N_NODES) {
                #pragma unroll
                for (int nt = 0; nt < 4; ++nt) {
                    const int n = wn * 32 + nt * 8 + (lane & 3) * 2;
                    float2 o;
                    o.x = c[mt][nt][h * 2 + 0] + bias2[nt].x;
                    o.y = c[mt][nt][h * 2 + 1] + bias2[nt].y;
                    if (RELU) { o.x = fmaxf(o.x, 0.f); o.y = fmaxf(o.y, 0.f); }
                    *(float2*)(hout + (size_t)row * DIM + n) = o;
                }
            }
        }
    }
}

extern "C" void kernel_launch(void* const* d_in, const int* in_sizes, int n_in,
                              void* d_out, int out_size)
{
    const float* x   = (const float*)d_in[0];
    const int*   adj = (const int*)  d_in[1];
    const float* W0  = (const float*)d_in[2];
    const float* b0  = (const float*)d_in[3];
    const float* W1  = (const float*)d_in[4];
    const float* b1  = (const float*)d_in[5];
    const float* W2  = (const float*)d_in[6];
    const float* b2  = (const float*)d_in[7];
    float* out = (float*)d_out;

    void *p0, *p1, *pwf;
    cudaGetSymbolAddress(&p0, g_buf0);
    cudaGetSymbolAddress(&p1, g_buf1);
    cudaGetSymbolAddress(&pwf, g_wfrag);
    float* h1 = (float*)p0;
    float* h2 = (float*)p1;
    const uint32_t* wf = (const uint32_t*)pwf;
    const size_t WSZ = 32 * 32 * 32 * 2;

    cudaFuncSetAttribute(sage_mma<true>,
                         cudaFuncAttributeMaxDynamicSharedMemorySize, SMEM_TOTAL);
    cudaFuncSetAttribute(sage_mma<false>,
                         cudaFuncAttributeMaxDynamicSharedMemorySize, SMEM_TOTAL);

    prep_wfrag<<<(3 * 32 * 32 * 32 + 255) / 256, 256>>>(W0, W1, W2);

    const int grid = N_NODES / BM;   // 3125
    sage_mma<true ><<<grid, THREADS, SMEM_TOTAL>>>(x,  adj, wf,           b0, h1);
    sage_mma<true ><<<grid, THREADS, SMEM_TOTAL>>>(h1, adj, wf + WSZ,     b1, h2);
    sage_mma<false><<<grid, THREADS, SMEM_TOTAL>>>(h2, adj, wf + 2 * WSZ, b2, out);
}

// round 13
// speedup vs baseline: 2.0587x; 1.4633x over previous
#include <cuda_runtime.h>
#include <cuda_fp16.h>
#include <cstdint>

// GraphSAGE on GB300, fp16 mma.sync + fp16-resident activations.
// R13: h stored fp16 (halves gather DRAM traffic), KC=64 (8 chunks, 32 MMAs
// per chunk, half the barriers). x pre-converted to fp16 once per launch.

#define N_NODES 100000
#define DIM     256
#define KDIM    512
#define NNEIGH  10
#define BM      32
#define KC      64
#define NCHUNK  8
#define THREADS 256

// smem (bytes)
#define ABUF    4096             // 32 rows x 128B (64 fp16 cols)
#define WBASE   8192
#define WBUF    32768            // per W buffer (fp16 frags, 32KB/chunk)
#define SMEM_TOTAL (WBASE + 2 * WBUF)   // 73728

__device__ __half g_h0[(size_t)N_NODES * DIM];   // fp16 x
__device__ __half g_h1[(size_t)N_NODES * DIM];
__device__ __half g_h2[(size_t)N_NODES * DIM];
// W fp16 fragments in mma B-frag order: [layer][ktile(32)][ntile(32)][lane(32)][2] u32
__device__ uint32_t g_wfrag[3][32 * 32 * 32 * 2];

__device__ __forceinline__ uint32_t smem_u32(const void* p) {
    uint32_t a;
    asm("{ .reg .u64 t; cvta.to.shared.u64 t, %1; cvt.u32.u64 %0, t; }" : "=r"(a) : "l"(p));
    return a;
}
__device__ __forceinline__ uint32_t sw128(uint32_t off) {
    return off ^ ((off >> 3) & 0x70);
}
__device__ __forceinline__ uint32_t pack_h2(float a, float b) {
    __half2 t = __floats2half2_rn(a, b);
    return *reinterpret_cast<uint32_t*>(&t);
}
__device__ __forceinline__ void ldmat4(uint32_t* r, uint32_t addr) {
    asm volatile("ldmatrix.sync.aligned.m8n8.x4.shared.b16 {%0,%1,%2,%3}, [%4];"
                 : "=r"(r[0]), "=r"(r[1]), "=r"(r[2]), "=r"(r[3]) : "r"(addr));
}
__device__ __forceinline__ void mma16816(float* c, const uint32_t* a, uint32_t b0, uint32_t b1) {
    asm volatile("mma.sync.aligned.m16n8k16.row.col.f32.f16.f16.f32 "
                 "{%0,%1,%2,%3}, {%4,%5,%6,%7}, {%8,%9}, {%0,%1,%2,%3};"
                 : "+f"(c[0]), "+f"(c[1]), "+f"(c[2]), "+f"(c[3])
                 : "r"(a[0]), "r"(a[1]), "r"(a[2]), "r"(a[3]), "r"(b0), "r"(b1));
}
__device__ __forceinline__ void cpasync16(uint32_t smem_dst, const void* gsrc) {
    asm volatile("cp.async.cg.shared.global [%0], [%1], 16;"
                 :: "r"(smem_dst), "l"(gsrc) : "memory");
}
__device__ __forceinline__ void cpasync_commit() {
    asm volatile("cp.async.commit_group;" ::: "memory");
}
__device__ __forceinline__ void cpasync_wait0() {
    asm volatile("cp.async.wait_group 0;" ::: "memory");
}

// -------- x -> fp16 convert --------
__global__ void conv_x(const float* __restrict__ x, __half* __restrict__ o)
{
    const size_t i = ((size_t)blockIdx.x * blockDim.x + threadIdx.x) * 8;
    if (i >= (size_t)N_NODES * DIM) return;
    const float4 a = *(const float4*)(x + i);
    const float4 b = *(const float4*)(x + i + 4);
    uint4 r;
    r.x = pack_h2(a.x, a.y); r.y = pack_h2(a.z, a.w);
    r.z = pack_h2(b.x, b.y); r.w = pack_h2(b.z, b.w);
    *(uint4*)(o + i) = r;
}

// -------- W prep: fp16 convert into mma B-fragment order --------
__global__ void prep_wfrag(const float* __restrict__ W0, const float* __restrict__ W1,
                           const float* __restrict__ W2)
{
    int idx = blockIdx.x * blockDim.x + threadIdx.x;   // [layer][kt][nt][lane]
    if (idx >= 3 * 32 * 32 * 32) return;
    const int lane  = idx & 31;
    const int nt    = (idx >> 5) & 31;
    const int kt    = (idx >> 10) & 31;
    const int layer = idx >> 15;
    const float* W = layer == 0 ? W0 : (layer == 1 ? W1 : W2);
    const int k0 = kt * 16 + (lane & 3) * 2;
    const int n  = nt * 8 + (lane >> 2);

    float v[4] = { W[(k0 + 0) * DIM + n], W[(k0 + 1) * DIM + n],
                   W[(k0 + 8) * DIM + n], W[(k0 + 9) * DIM + n] };
    const size_t base = ((size_t)(kt * 32 + nt) * 32 + lane) * 2;
    g_wfrag[layer][base + 0] = pack_h2(v[0], v[1]);
    g_wfrag[layer][base + 1] = pack_h2(v[2], v[3]);
}

// -------- fused SAGE layer --------
template <bool RELU, bool OUT32>
__global__ __launch_bounds__(THREADS, 2)
void sage_mma(const __half* __restrict__ hin, const int* __restrict__ adj,
              const uint32_t* __restrict__ wf,
              const float* __restrict__ bias, void* __restrict__ hout_v)
{
    extern __shared__ char smem[];
    const uint32_t sb = smem_u32(smem);
    const int tid  = threadIdx.x;
    const int lane = tid & 31;
    const int wn   = tid >> 5;       // warp n position (cols wn*32..+31)
    const int row0 = blockIdx.x * BM;

    // producer mapping: 8 threads/row, 8 fp16 cols each (16B)
    const int pr = tid >> 3;         // row 0..31
    const int pq = tid & 7;          // 8-col slice of the 64-col chunk
    const int prow = row0 + pr;

    float c[2][4][4];
    #pragma unroll
    for (int i = 0; i < 2; ++i)
        #pragma unroll
        for (int j = 0; j < 4; ++j)
            #pragma unroll
            for (int k = 0; k < 4; ++k) c[i][j][k] = 0.f;

    // ---- gather issue: 16B LDGs into rw (held across the MMA block) ----
    auto issue = [&](int kc, uint4* rw) {
        const int col = (kc & 3) * KC + pq * 8;     // fp16 column
        if (kc < 4) {
            rw[0] = *(const uint4*)(hin + (size_t)prow * DIM + col);
        } else {
            const int* arow = adj + (size_t)prow * NNEIGH;
            int na[NNEIGH];
            #pragma unroll
            for (int j = 0; j < NNEIGH; j += 2) {
                const int2 p = *(const int2*)(arow + j);
                na[j] = p.x; na[j + 1] = p.y;
            }
            #pragma unroll
            for (int j = 0; j < NNEIGH; ++j)
                rw[j] = *(const uint4*)(hin + (size_t)na[j] * DIM + col);
        }
    };
    // ---- gather consume: mean in fp32, pack fp16, swizzled A store ----
    auto consume = [&](int kc, const uint4* rw) {
        uint4 out;
        if (kc < 4) {
            out = rw[0];
        } else {
            float2 s[4];
            #pragma unroll
            for (int q = 0; q < 4; ++q) s[q] = make_float2(0.f, 0.f);
            #pragma unroll
            for (int j = 0; j < NNEIGH; ++j) {
                const uint32_t* u = (const uint32_t*)&rw[j];
                #pragma unroll
                for (int q = 0; q < 4; ++q) {
                    const __half2 h = *reinterpret_cast<const __half2*>(&u[q]);
                    const float2 f = __half22float2(h);
                    s[q].x += f.x; s[q].y += f.y;
                }
            }
            out.x = pack_h2(s[0].x * 0.1f, s[0].y * 0.1f);
            out.y = pack_h2(s[1].x * 0.1f, s[1].y * 0.1f);
            out.z = pack_h2(s[2].x * 0.1f, s[2].y * 0.1f);
            out.w = pack_h2(s[3].x * 0.1f, s[3].y * 0.1f);
        }
        char* Ab = smem + (kc & 1) * ABUF;
        *(uint4*)(Ab + sw128((uint32_t)(pr * 128 + pq * 16))) = out;
    };
    // ---- W chunk slab via cp.async (32KB) ----
    auto wcopy = [&](int kc) {
        const uint32_t dst = sb + WBASE + (kc & 1) * WBUF;
        const uint4* src = (const uint4*)(wf + (size_t)kc * 8192);
        #pragma unroll
        for (int i = 0; i < 8; ++i) {
            const int e = tid + i * THREADS;      // 2048 uint4 total
            cpasync16(dst + e * 16, src + e);
        }
        cpasync_commit();
    };

    // ================= prologue =================
    wcopy(0);
    {
        uint4 rw[NNEIGH];
        issue(0, rw);
        consume(0, rw);
    }
    cpasync_wait0();
    __syncthreads();

    // ================= main loop =================
    for (int kc = 0; kc < NCHUNK; ++kc) {
        const bool nxt = kc + 1 < NCHUNK;
        uint4 rw[NNEIGH];
        if (nxt) {
            wcopy(kc + 1);
            issue(kc + 1, rw);   // LDGs in flight across the MMA block
        }

        // ---- MMA on chunk kc: 4 kt x 8 = 32 MMAs ----
        const uint32_t Ab = sb + (kc & 1) * ABUF;
        const char*    Wp = smem + WBASE + (kc & 1) * WBUF;
        #pragma unroll
        for (int kt = 0; kt < 4; ++kt) {
            uint32_t a0[4], a1[4];
            const uint32_t off0 = (uint32_t)((lane & 15) * 128 + kt * 32 + (lane >> 4) * 16);
            ldmat4(a0, Ab + sw128(off0));
            ldmat4(a1, Ab + sw128(off0 + 16 * 128));

            const uint2* bp = (const uint2*)(Wp + ((size_t)(kt * 32 + wn * 4) * 32 + lane) * 8);
            uint2 b[4];
            #pragma unroll
            for (int nt = 0; nt < 4; ++nt) b[nt] = bp[nt * 32];
            #pragma unroll
            for (int nt = 0; nt < 4; ++nt) {          // 8 independent accumulators
                mma16816(c[0][nt], a0, b[nt].x, b[nt].y);
                mma16816(c[1][nt], a1, b[nt].x, b[nt].y);
            }
        }

        if (nxt) {
            consume(kc + 1, rw);   // data arrived during the MMA block
            cpasync_wait0();
        }
        __syncthreads();
    }

    // ================= epilogue =================
    float2 bias2[4];
    #pragma unroll
    for (int nt = 0; nt < 4; ++nt)
        bias2[nt] = *(const float2*)&bias[wn * 32 + nt * 8 + (lane & 3) * 2];

    #pragma unroll
    for (int mt = 0; mt < 2; ++mt) {
        const int rbase = row0 + mt * 16 + (lane >> 2);
        #pragma unroll
        for (int h = 0; h < 2; ++h) {
            const int row = rbase + h * 8;
            #pragma unroll
            for (int nt = 0; nt < 4; ++nt) {
                const int n = wn * 32 + nt * 8 + (lane & 3) * 2;
                float ox = c[mt][nt][h * 2 + 0] + bias2[nt].x;
                float oy = c[mt][nt][h * 2 + 1] + bias2[nt].y;
                if (RELU) { ox = fmaxf(ox, 0.f); oy = fmaxf(oy, 0.f); }
                if (OUT32) {
                    *(float2*)((float*)hout_v + (size_t)row * DIM + n) = make_float2(ox, oy);
                } else {
                    *(uint32_t*)((__half*)hout_v + (size_t)row * DIM + n) = pack_h2(ox, oy);
                }
            }
        }
    }
}

extern "C" void kernel_launch(void* const* d_in, const int* in_sizes, int n_in,
                              void* d_out, int out_size)
{
    const float* x   = (const float*)d_in[0];
    const int*   adj = (const int*)  d_in[1];
    const float* W0  = (const float*)d_in[2];
    const float* b0  = (const float*)d_in[3];
    const float* W1  = (const float*)d_in[4];
    const float* b1  = (const float*)d_in[5];
    const float* W2  = (const float*)d_in[6];
    const float* b2  = (const float*)d_in[7];
    float* out = (float*)d_out;

    void *p0, *p1, *p2, *pwf;
    cudaGetSymbolAddress(&p0, g_h0);
    cudaGetSymbolAddress(&p1, g_h1);
    cudaGetSymbolAddress(&p2, g_h2);
    cudaGetSymbolAddress(&pwf, g_wfrag);
    __half* xh = (__half*)p0;
    __half* h1 = (__half*)p1;
    __half* h2 = (__half*)p2;
    const uint32_t* wf = (const uint32_t*)pwf;
    const size_t WSZ = 32 * 32 * 32 * 2;

    cudaFuncSetAttribute((const void*)sage_mma<true, false>,
                         cudaFuncAttributeMaxDynamicSharedMemorySize, SMEM_TOTAL);
    cudaFuncSetAttribute((const void*)sage_mma<false, true>,
                         cudaFuncAttributeMaxDynamicSharedMemorySize, SMEM_TOTAL);

    prep_wfrag<<<(3 * 32 * 32 * 32 + 255) / 256, 256>>>(W0, W1, W2);
    conv_x<<<(N_NODES * DIM / 8 + 255) / 256, 256>>>(x, xh);

    const int grid = N_NODES / BM;   // 3125
    sage_mma<true,  false><<<grid, THREADS, SMEM_TOTAL>>>(xh, adj, wf,           b0, h1);
    sage_mma<true,  false><<<grid, THREADS, SMEM_TOTAL>>>(h1, adj, wf + WSZ,     b1, h2);
    sage_mma<false, true ><<<grid, THREADS, SMEM_TOTAL>>>(h2, adj, wf + 2 * WSZ, b2, out);
}

// round 14
// speedup vs baseline: 2.1373x; 1.0382x over previous
#include <cuda_runtime.h>
#include <cuda_fp16.h>
#include <cstdint>

// GraphSAGE on GB300, fp16 mma.sync + fp16-resident activations.
// R14: self chunks via direct cp.async into swizzled A slots (no reg round
// trip); neighbor mean uses level-1 pairwise __hadd2 then fp32 finish.

#define N_NODES 100000
#define DIM     256
#define KDIM    512
#define NNEIGH  10
#define BM      32
#define KC      64
#define NCHUNK  8
#define THREADS 256

// smem (bytes)
#define ABUF    4096             // 32 rows x 128B (64 fp16 cols)
#define WBASE   8192
#define WBUF    32768            // per W buffer (fp16 frags, 32KB/chunk)
#define SMEM_TOTAL (WBASE + 2 * WBUF)   // 73728

__device__ __half g_h0[(size_t)N_NODES * DIM];   // fp16 x
__device__ __half g_h1[(size_t)N_NODES * DIM];
__device__ __half g_h2[(size_t)N_NODES * DIM];
// W fp16 fragments in mma B-frag order: [layer][ktile(32)][ntile(32)][lane(32)][2] u32
__device__ uint32_t g_wfrag[3][32 * 32 * 32 * 2];

__device__ __forceinline__ uint32_t smem_u32(const void* p) {
    uint32_t a;
    asm("{ .reg .u64 t; cvta.to.shared.u64 t, %1; cvt.u32.u64 %0, t; }" : "=r"(a) : "l"(p));
    return a;
}
__device__ __forceinline__ uint32_t sw128(uint32_t off) {
    return off ^ ((off >> 3) & 0x70);
}
__device__ __forceinline__ uint32_t pack_h2(float a, float b) {
    __half2 t = __floats2half2_rn(a, b);
    return *reinterpret_cast<uint32_t*>(&t);
}
__device__ __forceinline__ void ldmat4(uint32_t* r, uint32_t addr) {
    asm volatile("ldmatrix.sync.aligned.m8n8.x4.shared.b16 {%0,%1,%2,%3}, [%4];"
                 : "=r"(r[0]), "=r"(r[1]), "=r"(r[2]), "=r"(r[3]) : "r"(addr));
}
__device__ __forceinline__ void mma16816(float* c, const uint32_t* a, uint32_t b0, uint32_t b1) {
    asm volatile("mma.sync.aligned.m16n8k16.row.col.f32.f16.f16.f32 "
                 "{%0,%1,%2,%3}, {%4,%5,%6,%7}, {%8,%9}, {%0,%1,%2,%3};"
                 : "+f"(c[0]), "+f"(c[1]), "+f"(c[2]), "+f"(c[3])
                 : "r"(a[0]), "r"(a[1]), "r"(a[2]), "r"(a[3]), "r"(b0), "r"(b1));
}
__device__ __forceinline__ void cpasync16(uint32_t smem_dst, const void* gsrc) {
    asm volatile("cp.async.cg.shared.global [%0], [%1], 16;"
                 :: "r"(smem_dst), "l"(gsrc) : "memory");
}
__device__ __forceinline__ void cpasync_commit() {
    asm volatile("cp.async.commit_group;" ::: "memory");
}
__device__ __forceinline__ void cpasync_wait0() {
    asm volatile("cp.async.wait_group 0;" ::: "memory");
}

// -------- x -> fp16 convert --------
__global__ void conv_x(const float* __restrict__ x, __half* __restrict__ o)
{
    const size_t i = ((size_t)blockIdx.x * blockDim.x + threadIdx.x) * 8;
    if (i >= (size_t)N_NODES * DIM) return;
    const float4 a = *(const float4*)(x + i);
    const float4 b = *(const float4*)(x + i + 4);
    uint4 r;
    r.x = pack_h2(a.x, a.y); r.y = pack_h2(a.z, a.w);
    r.z = pack_h2(b.x, b.y); r.w = pack_h2(b.z, b.w);
    *(uint4*)(o + i) = r;
}

// -------- W prep: fp16 convert into mma B-fragment order --------
__global__ void prep_wfrag(const float* __restrict__ W0, const float* __restrict__ W1,
                           const float* __restrict__ W2)
{
    int idx = blockIdx.x * blockDim.x + threadIdx.x;   // [layer][kt][nt][lane]
    if (idx >= 3 * 32 * 32 * 32) return;
    const int lane  = idx & 31;
    const int nt    = (idx >> 5) & 31;
    const int kt    = (idx >> 10) & 31;
    const int layer = idx >> 15;
    const float* W = layer == 0 ? W0 : (layer == 1 ? W1 : W2);
    const int k0 = kt * 16 + (lane & 3) * 2;
    const int n  = nt * 8 + (lane >> 2);

    float v[4] = { W[(k0 + 0) * DIM + n], W[(k0 + 1) * DIM + n],
                   W[(k0 + 8) * DIM + n], W[(k0 + 9) * DIM + n] };
    const size_t base = ((size_t)(kt * 32 + nt) * 32 + lane) * 2;
    g_wfrag[layer][base + 0] = pack_h2(v[0], v[1]);
    g_wfrag[layer][base + 1] = pack_h2(v[2], v[3]);
}

// -------- fused SAGE layer --------
template <bool RELU, bool OUT32>
__global__ __launch_bounds__(THREADS, 2)
void sage_mma(const __half* __restrict__ hin, const int* __restrict__ adj,
              const uint32_t* __restrict__ wf,
              const float* __restrict__ bias, void* __restrict__ hout_v)
{
    extern __shared__ char smem[];
    const uint32_t sb = smem_u32(smem);
    const int tid  = threadIdx.x;
    const int lane = tid & 31;
    const int wn   = tid >> 5;       // warp n position (cols wn*32..+31)
    const int row0 = blockIdx.x * BM;

    // producer mapping: 8 threads/row, 8 fp16 cols each (16B)
    const int pr = tid >> 3;         // row 0..31
    const int pq = tid & 7;          // 8-col slice of the 64-col chunk
    const int prow = row0 + pr;
    const uint32_t aslot = sw128((uint32_t)(pr * 128 + pq * 16));

    float c[2][4][4];
    #pragma unroll
    for (int i = 0; i < 2; ++i)
        #pragma unroll
        for (int j = 0; j < 4; ++j)
            #pragma unroll
            for (int k = 0; k < 4; ++k) c[i][j][k] = 0.f;

    // ---- self chunk: single cp.async straight into the swizzled A slot ----
    auto selfcopy = [&](int kc) {
        const int col = (kc & 3) * KC + pq * 8;
        cpasync16(sb + (kc & 1) * ABUF + aslot, hin + (size_t)prow * DIM + col);
    };
    // ---- neighbor gather issue: 16B LDGs into rw ----
    auto issue = [&](int kc, uint4* rw) {
        const int col = (kc & 3) * KC + pq * 8;
        const int* arow = adj + (size_t)prow * NNEIGH;
        int na[NNEIGH];
        #pragma unroll
        for (int j = 0; j < NNEIGH; j += 2) {
            const int2 p = *(const int2*)(arow + j);
            na[j] = p.x; na[j + 1] = p.y;
        }
        #pragma unroll
        for (int j = 0; j < NNEIGH; ++j)
            rw[j] = *(const uint4*)(hin + (size_t)na[j] * DIM + col);
    };
    // ---- neighbor consume: level-1 pairwise hadd2, fp32 finish ----
    auto consume = [&](int kc, const uint4* rw) {
        uint4 p[5];
        #pragma unroll
        for (int j = 0; j < 5; ++j) {
            const __half2* a = (const __half2*)&rw[2 * j];
            const __half2* b = (const __half2*)&rw[2 * j + 1];
            __half2* o = (__half2*)&p[j];
            #pragma unroll
            for (int q = 0; q < 4; ++q) o[q] = __hadd2(a[q], b[q]);
        }
        float2 s[4];
        #pragma unroll
        for (int q = 0; q < 4; ++q) s[q] = make_float2(0.f, 0.f);
        #pragma unroll
        for (int j = 0; j < 5; ++j) {
            const __half2* o = (const __half2*)&p[j];
            #pragma unroll
            for (int q = 0; q < 4; ++q) {
                const float2 f = __half22float2(o[q]);
                s[q].x += f.x; s[q].y += f.y;
            }
        }
        uint4 out;
        out.x = pack_h2(s[0].x * 0.1f, s[0].y * 0.1f);
        out.y = pack_h2(s[1].x * 0.1f, s[1].y * 0.1f);
        out.z = pack_h2(s[2].x * 0.1f, s[2].y * 0.1f);
        out.w = pack_h2(s[3].x * 0.1f, s[3].y * 0.1f);
        *(uint4*)(smem + (kc & 1) * ABUF + aslot) = out;
    };
    // ---- W chunk slab via cp.async (32KB), no commit inside ----
    auto wcopy = [&](int kc) {
        const uint32_t dst = sb + WBASE + (kc & 1) * WBUF;
        const uint4* src = (const uint4*)(wf + (size_t)kc * 8192);
        #pragma unroll
        for (int i = 0; i < 8; ++i) {
            const int e = tid + i * THREADS;      // 2048 uint4 total
            cpasync16(dst + e * 16, src + e);
        }
    };

    // ================= prologue =================
    wcopy(0);
    selfcopy(0);
    cpasync_commit();
    cpasync_wait0();
    __syncthreads();

    // ================= main loop =================
    for (int kc = 0; kc < NCHUNK; ++kc) {
        const bool nxt = kc + 1 < NCHUNK;
        uint4 rw[NNEIGH];
        if (nxt) {
            wcopy(kc + 1);
            if (kc + 1 < 4) {
                selfcopy(kc + 1);
                cpasync_commit();
            } else {
                cpasync_commit();
                issue(kc + 1, rw);   // LDGs in flight across the MMA block
            }
        }

        // ---- MMA on chunk kc: 4 kt x 8 = 32 MMAs ----
        const uint32_t Ab = sb + (kc & 1) * ABUF;
        const char*    Wp = smem + WBASE + (kc & 1) * WBUF;
        #pragma unroll
        for (int kt = 0; kt < 4; ++kt) {
            uint32_t a0[4], a1[4];
            const uint32_t off0 = (uint32_t)((lane & 15) * 128 + kt * 32 + (lane >> 4) * 16);
            ldmat4(a0, Ab + sw128(off0));
            ldmat4(a1, Ab + sw128(off0 + 16 * 128));

            const uint2* bp = (const uint2*)(Wp + ((size_t)(kt * 32 + wn * 4) * 32 + lane) * 8);
            uint2 b[4];
            #pragma unroll
            for (int nt = 0; nt < 4; ++nt) b[nt] = bp[nt * 32];
            #pragma unroll
            for (int nt = 0; nt < 4; ++nt) {          // 8 independent accumulators
                mma16816(c[0][nt], a0, b[nt].x, b[nt].y);
                mma16816(c[1][nt], a1, b[nt].x, b[nt].y);
            }
        }

        if (nxt) {
            if (kc + 1 >= 4) consume(kc + 1, rw);   // data arrived during MMAs
            cpasync_wait0();
        }
        __syncthreads();
    }

    // ================= epilogue =================
    float2 bias2[4];
    #pragma unroll
    for (int nt = 0; nt < 4; ++nt)
        bias2[nt] = *(const float2*)&bias[wn * 32 + nt * 8 + (lane & 3) * 2];

    #pragma unroll
    for (int mt = 0; mt < 2; ++mt) {
        const int rbase = row0 + mt * 16 + (lane >> 2);
        #pragma unroll
        for (int h = 0; h < 2; ++h) {
            const int row = rbase + h * 8;
            #pragma unroll
            for (int nt = 0; nt < 4; ++nt) {
                const int n = wn * 32 + nt * 8 + (lane & 3) * 2;
                float ox = c[mt][nt][h * 2 + 0] + bias2[nt].x;
                float oy = c[mt][nt][h * 2 + 1] + bias2[nt].y;
                if (RELU) { ox = fmaxf(ox, 0.f); oy = fmaxf(oy, 0.f); }
                if (OUT32) {
                    *(float2*)((float*)hout_v + (size_t)row * DIM + n) = make_float2(ox, oy);
                } else {
                    *(uint32_t*)((__half*)hout_v + (size_t)row * DIM + n) = pack_h2(ox, oy);
                }
            }
        }
    }
}

extern "C" void kernel_launch(void* const* d_in, const int* in_sizes, int n_in,
                              void* d_out, int out_size)
{
    const float* x   = (const float*)d_in[0];
    const int*   adj = (const int*)  d_in[1];
    const float* W0  = (const float*)d_in[2];
    const float* b0  = (const float*)d_in[3];
    const float* W1  = (const float*)d_in[4];
    const float* b1  = (const float*)d_in[5];
    const float* W2  = (const float*)d_in[6];
    const float* b2  = (const float*)d_in[7];
    float* out = (float*)d_out;

    void *p0, *p1, *p2, *pwf;
    cudaGetSymbolAddress(&p0, g_h0);
    cudaGetSymbolAddress(&p1, g_h1);
    cudaGetSymbolAddress(&p2, g_h2);
    cudaGetSymbolAddress(&pwf, g_wfrag);
    __half* xh = (__half*)p0;
    __half* h1 = (__half*)p1;
    __half* h2 = (__half*)p2;
    const uint32_t* wf = (const uint32_t*)pwf;
    const size_t WSZ = 32 * 32 * 32 * 2;

    cudaFuncSetAttribute((const void*)sage_mma<true, false>,
                         cudaFuncAttributeMaxDynamicSharedMemorySize, SMEM_TOTAL);
    cudaFuncSetAttribute((const void*)sage_mma<false, true>,
                         cudaFuncAttributeMaxDynamicSharedMemorySize, SMEM_TOTAL);

    prep_wfrag<<<(3 * 32 * 32 * 32 + 255) / 256, 256>>>(W0, W1, W2);
    conv_x<<<(N_NODES * DIM / 8 + 255) / 256, 256>>>(x, xh);

    const int grid = N_NODES / BM;   // 3125
    sage_mma<true,  false><<<grid, THREADS, SMEM_TOTAL>>>(xh, adj, wf,           b0, h1);
    sage_mma<true,  false><<<grid, THREADS, SMEM_TOTAL>>>(h1, adj, wf + WSZ,     b1, h2);
    sage_mma<false, true ><<<grid, THREADS, SMEM_TOTAL>>>(h2, adj, wf + 2 * WSZ, b2, out);
}